// round 4
// baseline (speedup 1.0000x reference)
#include <cuda_runtime.h>
#include <cuda_fp16.h>
#include <cstdint>
#include <cstddef>

#define BATCH 2048
#define SN 64         // S
#define EN 256        // E
#define DN 512        // D
#define INN 32        // IN
#define TN 64         // T
#define KA 544        // D + IN
#define N4D 2048      // 4*D
#define NB 768        // fused output: p (512) | u (256)
#define SEQLEN 96     // 31 hist + 64 cur + 1 pad

// ---------------- scratch (__device__ globals; no allocation) ----------------
__device__ __align__(16) __half g_enc[(size_t)BATCH * SN * EN];   // fp16 encoder
__device__ __align__(16) __half g_Xcat[(size_t)BATCH * KA];       // [h fp16 | x fp16]
__device__ __align__(16) float  g_c[(size_t)BATCH * DN];          // LSTM cell state
__device__ __align__(16) float  g_H[(size_t)BATCH * DN];          // h2 fp32 (for attn)
__device__ __align__(16) float  g_gates[(size_t)BATCH * N4D];     // gates fp32
__device__ __align__(16) float  g_Pout[(size_t)BATCH * NB];       // p,u fp32
__device__ __align__(16) __half g_WgT[(size_t)KA * N4D];          // gate weights [K][N]
__device__ __align__(16) __half g_WbT[(size_t)DN * NB];           // [K][N] for p/u
__device__ __align__(16) __half g_WiT[(size_t)288 * 1024];        // init weights [K][N]
__device__ __align__(16) __half g_Inp[(size_t)BATCH * 288];       // [mean_enc | speed0]
__device__ __align__(16) float  g_gb[N4D];                        // b_ih + b_hh
__device__ __align__(16) float  g_seq[(size_t)BATCH * SEQLEN];    // speed sequence

// ---------------- fp16 TC GEMM: C[M,N] = A[M,K] * Bt[K,N], fp32 accum ----------------
#define BM 128
#define BN 128
#define BK 32

__device__ __forceinline__ uint32_t smem_u32(const void* p) {
    return (uint32_t)__cvta_generic_to_shared(p);
}
__device__ __forceinline__ void cp16(uint32_t dst, const void* src) {
    asm volatile("cp.async.cg.shared.global [%0], [%1], 16;\n" :: "r"(dst), "l"(src));
}

template<int K, int LDA, int LDB, int LDC>
__device__ __forceinline__ void gemm_core(const __half* __restrict__ A,
                                          const __half* __restrict__ Bt,
                                          float* __restrict__ C)
{
    __shared__ __align__(16) __half As[2][BM][BK + 8];
    __shared__ __align__(16) __half Bs[2][BK][BN + 8];

    const int tid  = threadIdx.x;
    const int lane = tid & 31;
    const int warp = tid >> 5;
    const int wm   = warp & 1;     // 2 M-warps of 64 rows
    const int wn   = warp >> 1;    // 4 N-warps of 32 cols
    const int bm   = blockIdx.y * BM;
    const int bn   = blockIdx.x * BN;

    float acc[4][4][4];
#pragma unroll
    for (int a = 0; a < 4; a++)
#pragma unroll
        for (int b = 0; b < 4; b++)
#pragma unroll
            for (int c = 0; c < 4; c++) acc[a][b][c] = 0.f;

    const int am  = tid >> 2;      // 0..63 (A rows; +64 second half)
    const int akq = tid & 3;       // 8-half chunk of BK
    const int bk  = tid >> 4;      // 0..15 (B rows; +16 second half)
    const int bnq = tid & 15;      // 8-half chunk of BN

    auto load_async = [&](int kt, int buf) {
        const int k0 = kt * BK;
        cp16(smem_u32(&As[buf][am][akq * 8]),
             A + (size_t)(bm + am) * LDA + k0 + akq * 8);
        cp16(smem_u32(&As[buf][am + 64][akq * 8]),
             A + (size_t)(bm + am + 64) * LDA + k0 + akq * 8);
        cp16(smem_u32(&Bs[buf][bk][bnq * 8]),
             Bt + (size_t)(k0 + bk) * LDB + bn + bnq * 8);
        cp16(smem_u32(&Bs[buf][bk + 16][bnq * 8]),
             Bt + (size_t)(k0 + bk + 16) * LDB + bn + bnq * 8);
        asm volatile("cp.async.commit_group;\n");
    };

    constexpr int KT = K / BK;
    load_async(0, 0);

    for (int kt = 0; kt < KT; kt++) {
        const int buf = kt & 1;
        if (kt + 1 < KT) {
            load_async(kt + 1, buf ^ 1);
            asm volatile("cp.async.wait_group 1;\n");
        } else {
            asm volatile("cp.async.wait_group 0;\n");
        }
        __syncthreads();

#pragma unroll
        for (int kk = 0; kk < 2; kk++) {
            uint32_t af[4][4], bf[4][2];
#pragma unroll
            for (int im = 0; im < 4; im++) {
                uint32_t addr = smem_u32(
                    &As[buf][wm * 64 + im * 16 + (lane & 15)][kk * 16 + (lane >> 4) * 8]);
                asm volatile("ldmatrix.sync.aligned.m8n8.x4.shared.b16 {%0,%1,%2,%3}, [%4];\n"
                             : "=r"(af[im][0]), "=r"(af[im][1]), "=r"(af[im][2]), "=r"(af[im][3])
                             : "r"(addr));
            }
#pragma unroll
            for (int in = 0; in < 4; in++) {
                uint32_t addr = smem_u32(&Bs[buf][kk * 16 + (lane & 15)][wn * 32 + in * 8]);
                asm volatile("ldmatrix.sync.aligned.m8n8.x2.trans.shared.b16 {%0,%1}, [%2];\n"
                             : "=r"(bf[in][0]), "=r"(bf[in][1])
                             : "r"(addr));
            }
#pragma unroll
            for (int im = 0; im < 4; im++)
#pragma unroll
                for (int in = 0; in < 4; in++)
                    asm volatile("mma.sync.aligned.m16n8k16.row.col.f32.f16.f16.f32 "
                                 "{%0,%1,%2,%3}, {%4,%5,%6,%7}, {%8,%9}, {%0,%1,%2,%3};\n"
                                 : "+f"(acc[im][in][0]), "+f"(acc[im][in][1]),
                                   "+f"(acc[im][in][2]), "+f"(acc[im][in][3])
                                 : "r"(af[im][0]), "r"(af[im][1]), "r"(af[im][2]), "r"(af[im][3]),
                                   "r"(bf[in][0]), "r"(bf[in][1]));
        }
        __syncthreads();
    }

#pragma unroll
    for (int im = 0; im < 4; im++) {
        const int r = bm + wm * 64 + im * 16 + (lane >> 2);
#pragma unroll
        for (int in = 0; in < 4; in++) {
            const int cc = bn + wn * 32 + in * 8 + (lane & 3) * 2;
            *(float2*)(C + (size_t)r * LDC + cc)       = make_float2(acc[im][in][0], acc[im][in][1]);
            *(float2*)(C + (size_t)(r + 8) * LDC + cc) = make_float2(acc[im][in][2], acc[im][in][3]);
        }
    }
}

__global__ __launch_bounds__(256, 2) void gemmA_kernel() {            // gates
    gemm_core<KA, KA, N4D, N4D>(g_Xcat, g_WgT, g_gates);
}
__global__ __launch_bounds__(256, 2) void gemmB_kernel() {            // p | u
    gemm_core<DN, KA, NB, NB>(g_Xcat, g_WbT, g_Pout);
}
__global__ __launch_bounds__(256, 2) void gemmI_kernel() {            // h0 | c0
    gemm_core<288, 288, 1024, 1024>(g_Inp, g_WiT, g_gates);
}

// ---------------- init / pack kernels ----------------
__global__ void pack_wg(const float* __restrict__ W_hh, const float* __restrict__ W_ih,
                        const float* __restrict__ b_ih, const float* __restrict__ b_hh) {
    int idx = blockIdx.x * 256 + threadIdx.x;
    if (idx < KA * N4D) {
        int k = idx / N4D, n = idx - k * N4D;
        float v = (k < DN) ? W_hh[(size_t)n * DN + k] : W_ih[(size_t)n * INN + (k - DN)];
        g_WgT[idx] = __float2half(v);
    }
    if (idx < N4D) g_gb[idx] = b_ih[idx] + b_hh[idx];
}
__global__ void pack_wb(const float* __restrict__ W_wp, const float* __restrict__ W_wa) {
    int idx = blockIdx.x * 256 + threadIdx.x;
    if (idx >= DN * NB) return;
    int k = idx / NB, n = idx - k * NB;
    float v = (n < DN) ? W_wp[(size_t)n * DN + k]          // p_d = sum_k W_wp[d,k] h_k
                       : W_wa[(size_t)k * EN + (n - DN)];  // u_e = sum_d W_wa[d,e] h_d
    g_WbT[idx] = __float2half(v);
}
__global__ void pack_wi(const float* __restrict__ W_init_h, const float* __restrict__ W_init_c) {
    int idx = blockIdx.x * 256 + threadIdx.x;
    if (idx >= 288 * 1024) return;
    int k = idx / 1024, n = idx - k * 1024;
    float v = (n < DN) ? W_init_h[(size_t)n * 288 + k] : W_init_c[(size_t)(n - DN) * 288 + k];
    g_WiT[idx] = __float2half(v);
}
__global__ void enc_convert(const float* __restrict__ src) {
    size_t i = (size_t)blockIdx.x * 256 + threadIdx.x;
    const size_t n4 = (size_t)BATCH * SN * EN / 4;
    if (i >= n4) return;
    float4 v = ((const float4*)src)[i];
    __half2* dst = (__half2*)g_enc;
    dst[2 * i]     = __floats2half2_rn(v.x, v.y);
    dst[2 * i + 1] = __floats2half2_rn(v.z, v.w);
}
__global__ void seq_build(const float* __restrict__ hist, const float* __restrict__ cur) {
    int idx = blockIdx.x * 256 + threadIdx.x;
    if (idx >= BATCH * SEQLEN) return;
    int b = idx / SEQLEN, j = idx - b * SEQLEN;
    float v = (j < 31) ? hist[(size_t)b * 31 + j]
            : (j < 95) ? cur[(size_t)b * TN + (j - 31)] : 0.f;
    g_seq[idx] = v;
}
__global__ void mean_inp(const float* __restrict__ cEnc) {
    int b = blockIdx.x, tid = threadIdx.x;
    const float* p = cEnc + (size_t)b * SN * EN + tid;
    float s = 0.f;
#pragma unroll 8
    for (int i = 0; i < SN; i++) s += p[(size_t)i * EN];
    g_Inp[(size_t)b * 288 + tid] = __float2half(s * (1.f / 64.f));
    if (tid < INN)
        g_Inp[(size_t)b * 288 + EN + tid] = __float2half(g_seq[(size_t)b * SEQLEN + tid]);
}
__global__ void init_finish(const float* __restrict__ b_init_h, const float* __restrict__ b_init_c) {
    int idx = blockIdx.x * 256 + threadIdx.x;
    if (idx >= BATCH * KA) return;
    int b = idx / KA, d = idx - b * KA;
    if (d < DN) {
        float h0 = g_gates[(size_t)b * 1024 + d] + b_init_h[d];
        float c0 = g_gates[(size_t)b * 1024 + DN + d] + b_init_c[d];
        g_c[(size_t)b * DN + d] = c0;
        g_Xcat[idx] = __float2half(h0);
    } else {
        g_Xcat[idx] = __float2half(g_seq[(size_t)b * SEQLEN + (d - DN)]);  // x_0 = seq[0:32]
    }
}

// -------- per-step pointwise LSTM + pack next-step operand [h2 | x_{t+1}] --------
__global__ __launch_bounds__(256) void lstm_step(int t) {
    int idx = blockIdx.x * 256 + threadIdx.x;
    if (idx >= BATCH * KA) return;
    int b = idx / KA, d = idx - b * KA;
    if (d < DN) {
        const float* gr = g_gates + (size_t)b * N4D;
        float xi = gr[d]          + g_gb[d];
        float xf = gr[DN + d]     + g_gb[DN + d];
        float xg = gr[2 * DN + d] + g_gb[2 * DN + d];
        float xo = gr[3 * DN + d] + g_gb[3 * DN + d];
        float si = 1.f / (1.f + expf(-xi));
        float sf = 1.f / (1.f + expf(-xf));
        float so = 1.f / (1.f + expf(-xo));
        float c2 = sf * g_c[(size_t)b * DN + d] + si * tanhf(xg);
        float h2 = so * tanhf(c2);
        g_c[(size_t)b * DN + d] = c2;
        g_H[(size_t)b * DN + d] = h2;
        g_Xcat[idx] = __float2half(h2);
    } else {
        g_Xcat[idx] = __float2half(g_seq[(size_t)b * SEQLEN + t + 1 + (d - DN)]);
    }
}

// ---------------- per-step attention / alignment / prediction ----------------
__global__ __launch_bounds__(256) void attn_step(const float* __restrict__ b_wp,
                                                 const float* __restrict__ W_vp,
                                                 const float* __restrict__ b_vp,
                                                 const float* __restrict__ W_fc,
                                                 const float* __restrict__ b_fc,
                                                 float* __restrict__ outPred,
                                                 float* __restrict__ outAlpha, int t) {
    const int b = blockIdx.x, tid = threadIdx.x;
    __shared__ __align__(16) __half sEnc[SN * EN];   // 32 KB
    __shared__ float sU[EN];
    __shared__ float sAtt[SN];
    __shared__ float sAlpha[SN];
    __shared__ float sRed[8];
    __shared__ float sAligned;

    // encoder tile -> smem
    const uint4* ge = (const uint4*)(g_enc + (size_t)b * SN * EN);
    uint4* se = (uint4*)sEnc;
#pragma unroll
    for (int i = 0; i < 8; i++) se[tid + i * 256] = ge[tid + i * 256];

    sU[tid] = g_Pout[(size_t)b * NB + DN + tid];  // u_e

    // aligned = S * sigmoid( sum_d tanh(p_d + b_wp_d) * W_vp_d + b_vp )
    float part = 0.f;
#pragma unroll
    for (int it = 0; it < 2; it++) {
        int d = tid + it * 256;
        part += tanhf(g_Pout[(size_t)b * NB + d] + b_wp[d]) * W_vp[d];
    }
#pragma unroll
    for (int o = 16; o; o >>= 1) part += __shfl_xor_sync(0xffffffffu, part, o);
    if ((tid & 31) == 0) sRed[tid >> 5] = part;
    __syncthreads();
    if (tid == 0) {
        float tot = 0.f;
#pragma unroll
        for (int i = 0; i < 8; i++) tot += sRed[i];
        tot += b_vp[0];
        sAligned = (float)SN / (1.f + expf(-tot));
    }
    __syncthreads();
    const float aligned = sAligned;

    // att_s = <enc_s, u> : quad of threads per s
    {
        int s = tid >> 2, q = tid & 3;
        const __half* er = sEnc + s * EN;
        float a = 0.f;
#pragma unroll 16
        for (int e = q; e < EN; e += 4) a += __half2float(er[e]) * sU[e];
        a += __shfl_xor_sync(0xffffffffu, a, 1);
        a += __shfl_xor_sync(0xffffffffu, a, 2);
        if (q == 0) sAtt[s] = a;
    }
    __syncthreads();

    // softmax over S=64 + Gaussian window (warp 0, 2 values/lane)
    if (tid < 32) {
        float a0 = sAtt[tid], a1 = sAtt[tid + 32];
        float m = fmaxf(a0, a1);
#pragma unroll
        for (int o = 16; o; o >>= 1) m = fmaxf(m, __shfl_xor_sync(0xffffffffu, m, o));
        float e0 = expf(a0 - m), e1 = expf(a1 - m);
        float s2 = e0 + e1;
#pragma unroll
        for (int o = 16; o; o >>= 1) s2 += __shfl_xor_sync(0xffffffffu, s2, o);
        float inv = 1.f / s2;
        float d0 = (float)tid - aligned, d1 = (float)(tid + 32) - aligned;
        sAlpha[tid]      = e0 * inv * expf(-0.5f * d0 * d0);
        sAlpha[tid + 32] = e1 * inv * expf(-0.5f * d1 * d1);
    }
    __syncthreads();

    if (tid < SN)
        outAlpha[((size_t)b * TN + t) * SN + tid] = sAlpha[tid];

    // awe_e = sum_s enc[s,e]*alpha_s ; pred partial with [awe | h2] @ W_fc
    float awe = 0.f;
#pragma unroll 16
    for (int s = 0; s < SN; s++) awe += __half2float(sEnc[s * EN + tid]) * sAlpha[s];

    const float* hrow = g_H + (size_t)b * DN;
    float pp = awe * W_fc[tid]
             + hrow[tid]       * W_fc[EN + tid]
             + hrow[tid + 256] * W_fc[EN + 256 + tid];
#pragma unroll
    for (int o = 16; o; o >>= 1) pp += __shfl_xor_sync(0xffffffffu, pp, o);
    if ((tid & 31) == 0) sRed[tid >> 5] = pp;
    __syncthreads();
    if (tid == 0) {
        float tot = 0.f;
#pragma unroll
        for (int i = 0; i < 8; i++) tot += sRed[i];
        outPred[(size_t)b * TN + t] = tot + b_fc[0];
    }
}

// ---------------- launcher ----------------
extern "C" void kernel_launch(void* const* d_in, const int* in_sizes, int n_in,
                              void* d_out, int out_size) {
    const float* cEnc       = (const float*)d_in[0];
    const float* curSpeeds  = (const float*)d_in[1];
    const float* histSpeeds = (const float*)d_in[2];
    // slot 5 is decodeLength (scalar) if present; weights start after it
    int wo = (n_in > 5 && in_sizes[5] == 1) ? 6 : 5;
    const float* W_init_h = (const float*)d_in[wo + 0];
    const float* b_init_h = (const float*)d_in[wo + 1];
    const float* W_init_c = (const float*)d_in[wo + 2];
    const float* b_init_c = (const float*)d_in[wo + 3];
    const float* W_ih     = (const float*)d_in[wo + 4];
    const float* W_hh     = (const float*)d_in[wo + 5];
    const float* b_ih     = (const float*)d_in[wo + 6];
    const float* b_hh     = (const float*)d_in[wo + 7];
    const float* W_wa     = (const float*)d_in[wo + 8];
    // b_wa (wo+9) is softmax-invariant: unused
    const float* W_wp     = (const float*)d_in[wo + 10];
    const float* b_wp     = (const float*)d_in[wo + 11];
    const float* W_vp     = (const float*)d_in[wo + 12];
    const float* b_vp     = (const float*)d_in[wo + 13];
    const float* W_fc     = (const float*)d_in[wo + 14];
    const float* b_fc     = (const float*)d_in[wo + 15];

    float* outPred  = (float*)d_out;                 // [B,T,1]
    float* outAlpha = outPred + (size_t)BATCH * TN;  // [B,T,S]

    enc_convert<<<32768, 256>>>(cEnc);
    seq_build<<<(BATCH * SEQLEN) / 256, 256>>>(histSpeeds, curSpeeds);
    pack_wg<<<(KA * N4D) / 256, 256>>>(W_hh, W_ih, b_ih, b_hh);
    pack_wb<<<(DN * NB) / 256, 256>>>(W_wp, W_wa);
    pack_wi<<<(288 * 1024) / 256, 256>>>(W_init_h, W_init_c);
    mean_inp<<<BATCH, 256>>>(cEnc);
    gemmI_kernel<<<dim3(1024 / BN, BATCH / BM), 256>>>();
    init_finish<<<(BATCH * KA) / 256, 256>>>(b_init_h, b_init_c);

    for (int t = 0; t < TN; t++) {
        gemmA_kernel<<<dim3(N4D / BN, BATCH / BM), 256>>>();
        lstm_step<<<(BATCH * KA) / 256, 256>>>(t);
        gemmB_kernel<<<dim3(NB / BN, BATCH / BM), 256>>>();
        attn_step<<<BATCH, 256>>>(b_wp, W_vp, b_vp, W_fc, b_fc, outPred, outAlpha, t);
    }
}

// round 6
// speedup vs baseline: 1.2261x; 1.2261x over previous
#include <cuda_runtime.h>
#include <cuda_fp16.h>
#include <cstdint>
#include <cstddef>

#define BATCH 2048
#define SN 64         // S
#define EN 256        // E
#define EN2 264       // padded smem row (conflict-free att)
#define DN 512        // D
#define INN 32        // IN
#define TN 64         // T
#define KA 544        // D + IN
#define N4D 2048      // 4*D (gate cols, interleaved n=4d+g)
#define NF 2816       // fused cols: 2048 gates | 512 p | 256 u
#define NB 768        // p|u rows in g_Pout
#define SEQLEN 128    // 31 hist + 64 cur + pad

// ---------------- scratch (__device__ globals; no allocation) ----------------
__device__ __align__(16) __half g_enc[(size_t)BATCH * SN * EN];    // fp16 encoder
__device__ __align__(16) __half g_Xcat[2][(size_t)BATCH * KA];     // [h fp16 | x fp16], double buf
__device__ __align__(16) float  g_c[(size_t)BATCH * DN];           // LSTM cell state
__device__ __align__(16) float  g_H[2][(size_t)BATCH * DN];        // h2 fp32, double buf
__device__ __align__(16) float  g_gates[(size_t)BATCH * N4D];      // init GEMM output only
__device__ __align__(16) float  g_Pout[(size_t)BATCH * NB];        // p,u fp32
__device__ __align__(16) __half g_WfT[(size_t)KA * NF];            // fused weights [K][N]
__device__ __align__(16) __half g_WiT[(size_t)288 * 1024];         // init weights [K][N]
__device__ __align__(16) __half g_Inp[(size_t)BATCH * 288];        // [mean_enc | speed0]
__device__ __align__(16) float  g_gb[N4D];                         // (b_ih+b_hh) interleaved 4d+g
__device__ __align__(16) float  g_seq[(size_t)BATCH * SEQLEN];     // speed sequence

// ---------------- fp16 TC GEMM mainloop: acc += A[M,K] * Bt[K,N] ----------------
#define BM 128
#define BN 128
#define BK 32

__device__ __forceinline__ uint32_t smem_u32(const void* p) {
    return (uint32_t)__cvta_generic_to_shared(p);
}
__device__ __forceinline__ void cp16(uint32_t dst, const void* src) {
    asm volatile("cp.async.cg.shared.global [%0], [%1], 16;\n" :: "r"(dst), "l"(src));
}

template<int K, int LDA, int LDB>
__device__ __forceinline__ void gemm_mainloop(const __half* __restrict__ A,
                                              const __half* __restrict__ Bt,
                                              int bm, int bn,
                                              float acc[4][4][4])
{
    __shared__ __align__(16) __half As[2][BM][BK + 8];
    __shared__ __align__(16) __half Bs[2][BK][BN + 8];

    const int tid  = threadIdx.x;
    const int lane = tid & 31;
    const int warp = tid >> 5;
    const int wm   = warp & 1;
    const int wn   = warp >> 1;

#pragma unroll
    for (int a = 0; a < 4; a++)
#pragma unroll
        for (int b = 0; b < 4; b++)
#pragma unroll
            for (int c = 0; c < 4; c++) acc[a][b][c] = 0.f;

    const int am  = tid >> 2;
    const int akq = tid & 3;
    const int bk  = tid >> 4;
    const int bnq = tid & 15;

    auto load_async = [&](int kt, int buf) {
        const int k0 = kt * BK;
        cp16(smem_u32(&As[buf][am][akq * 8]),
             A + (size_t)(bm + am) * LDA + k0 + akq * 8);
        cp16(smem_u32(&As[buf][am + 64][akq * 8]),
             A + (size_t)(bm + am + 64) * LDA + k0 + akq * 8);
        cp16(smem_u32(&Bs[buf][bk][bnq * 8]),
             Bt + (size_t)(k0 + bk) * LDB + bn + bnq * 8);
        cp16(smem_u32(&Bs[buf][bk + 16][bnq * 8]),
             Bt + (size_t)(k0 + bk + 16) * LDB + bn + bnq * 8);
        asm volatile("cp.async.commit_group;\n");
    };

    constexpr int KT = K / BK;
    load_async(0, 0);

    for (int kt = 0; kt < KT; kt++) {
        const int buf = kt & 1;
        if (kt + 1 < KT) {
            load_async(kt + 1, buf ^ 1);
            asm volatile("cp.async.wait_group 1;\n");
        } else {
            asm volatile("cp.async.wait_group 0;\n");
        }
        __syncthreads();

#pragma unroll
        for (int kk = 0; kk < 2; kk++) {
            uint32_t af[4][4], bf[4][2];
#pragma unroll
            for (int im = 0; im < 4; im++) {
                uint32_t addr = smem_u32(
                    &As[buf][wm * 64 + im * 16 + (lane & 15)][kk * 16 + (lane >> 4) * 8]);
                asm volatile("ldmatrix.sync.aligned.m8n8.x4.shared.b16 {%0,%1,%2,%3}, [%4];\n"
                             : "=r"(af[im][0]), "=r"(af[im][1]), "=r"(af[im][2]), "=r"(af[im][3])
                             : "r"(addr));
            }
#pragma unroll
            for (int in = 0; in < 4; in++) {
                uint32_t addr = smem_u32(&Bs[buf][kk * 16 + (lane & 15)][wn * 32 + in * 8]);
                asm volatile("ldmatrix.sync.aligned.m8n8.x2.trans.shared.b16 {%0,%1}, [%2];\n"
                             : "=r"(bf[in][0]), "=r"(bf[in][1])
                             : "r"(addr));
            }
#pragma unroll
            for (int im = 0; im < 4; im++)
#pragma unroll
                for (int in = 0; in < 4; in++)
                    asm volatile("mma.sync.aligned.m16n8k16.row.col.f32.f16.f16.f32 "
                                 "{%0,%1,%2,%3}, {%4,%5,%6,%7}, {%8,%9}, {%0,%1,%2,%3};\n"
                                 : "+f"(acc[im][in][0]), "+f"(acc[im][in][1]),
                                   "+f"(acc[im][in][2]), "+f"(acc[im][in][3])
                                 : "r"(af[im][0]), "r"(af[im][1]), "r"(af[im][2]), "r"(af[im][3]),
                                   "r"(bf[in][0]), "r"(bf[in][1]));
        }
        __syncthreads();
    }
}

// ---------------- fused per-step kernel: gates_t (+LSTM) and pu of h_prev ----------------
// Reads Xcat[t&1] = (h_prev | x_t). Gate tiles (bn<2048, cols interleaved 4d+g)
// run the LSTM in the epilogue and write h_t -> Xcat[(t+1)&1], g_H[t&1], g_c.
// pu tiles (bn>=2048) store p,u (computed from h_prev) into g_Pout.
__global__ __launch_bounds__(256, 2) void fused_step(int t) {
    const __half* A  = g_Xcat[t & 1];
    __half* Xout     = g_Xcat[(t + 1) & 1];
    float*  Hout     = g_H[t & 1];
    const int bm = blockIdx.y * BM;
    const int bn = blockIdx.x * BN;

    float acc[4][4][4];
    gemm_mainloop<KA, KA, NF>(A, g_WfT, bm, bn, acc);

    const int tid  = threadIdx.x;
    const int lane = tid & 31;
    const int warp = tid >> 5;
    const int wm   = warp & 1;
    const int wn   = warp >> 1;

    if (bn < N4D) {
        // ---- LSTM epilogue on interleaved gate columns ----
        const int pair_sel = lane & 1;
#pragma unroll
        for (int im = 0; im < 4; im++) {
            const int r = bm + wm * 64 + im * 16 + (lane >> 2);
#pragma unroll
            for (int in = 0; in < 4; in++) {
                const int ccg = bn + wn * 32 + in * 8 + (lane & 3) * 2;
                float b0 = __ldg(&g_gb[ccg]);
                float b1 = __ldg(&g_gb[ccg + 1]);
                float a0 = acc[im][in][0] + b0;
                float a1 = acc[im][in][1] + b1;
                float a2 = acc[im][in][2] + b0;
                float a3 = acc[im][in][3] + b1;
                float o0 = __shfl_xor_sync(0xffffffffu, a0, 1);
                float o1 = __shfl_xor_sync(0xffffffffu, a1, 1);
                float o2 = __shfl_xor_sync(0xffffffffu, a2, 1);
                float o3 = __shfl_xor_sync(0xffffffffu, a3, 1);
                int row; float xi, xf, xg, xo;
                if (pair_sel == 0) { row = r;     xi = a0; xf = a1; xg = o0; xo = o1; }
                else               { row = r + 8; xi = o2; xf = o3; xg = a2; xo = a3; }
                const int d = ((bn + wn * 32 + in * 8) >> 2) + ((lane & 3) >> 1);
                float si = 1.f / (1.f + expf(-xi));
                float sf = 1.f / (1.f + expf(-xf));
                float so = 1.f / (1.f + expf(-xo));
                float c2 = sf * g_c[(size_t)row * DN + d] + si * tanhf(xg);
                float h2 = so * tanhf(c2);
                g_c[(size_t)row * DN + d]  = c2;
                Hout[(size_t)row * DN + d] = h2;
                Xout[(size_t)row * KA + d] = __float2half(h2);
            }
        }
    } else {
        // ---- p|u store ----
#pragma unroll
        for (int im = 0; im < 4; im++) {
            const int r = bm + wm * 64 + im * 16 + (lane >> 2);
#pragma unroll
            for (int in = 0; in < 4; in++) {
                const int cc = bn - N4D + wn * 32 + in * 8 + (lane & 3) * 2;
                *(float2*)(g_Pout + (size_t)r * NB + cc) =
                    make_float2(acc[im][in][0], acc[im][in][1]);
                *(float2*)(g_Pout + (size_t)(r + 8) * NB + cc) =
                    make_float2(acc[im][in][2], acc[im][in][3]);
            }
        }
        // the first pu block per row-band also writes x_{t+1} into Xout
        if (bn == N4D) {
            const int rrow = bm + (tid >> 1);
            const int jb = (tid & 1) * 16;
#pragma unroll
            for (int j = 0; j < 16; j++) {
                int jj = jb + j;
                Xout[(size_t)rrow * KA + DN + jj] =
                    __float2half(g_seq[(size_t)rrow * SEQLEN + t + 1 + jj]);
            }
        }
    }
}

// ---------------- init GEMM (h0|c0) ----------------
__global__ __launch_bounds__(256, 2) void gemmI_kernel() {
    float acc[4][4][4];
    const int bm = blockIdx.y * BM;
    const int bn = blockIdx.x * BN;
    gemm_mainloop<288, 288, 1024>(g_Inp, g_WiT, bm, bn, acc);
    const int tid  = threadIdx.x;
    const int lane = tid & 31;
    const int warp = tid >> 5;
    const int wm   = warp & 1;
    const int wn   = warp >> 1;
#pragma unroll
    for (int im = 0; im < 4; im++) {
        const int r = bm + wm * 64 + im * 16 + (lane >> 2);
#pragma unroll
        for (int in = 0; in < 4; in++) {
            const int cc = bn + wn * 32 + in * 8 + (lane & 3) * 2;
            *(float2*)(g_gates + (size_t)r * 1024 + cc) =
                make_float2(acc[im][in][0], acc[im][in][1]);
            *(float2*)(g_gates + (size_t)(r + 8) * 1024 + cc) =
                make_float2(acc[im][in][2], acc[im][in][3]);
        }
    }
}

// ---------------- init / pack kernels ----------------
__global__ void pack_wf(const float* __restrict__ W_hh, const float* __restrict__ W_ih,
                        const float* __restrict__ W_wp, const float* __restrict__ W_wa,
                        const float* __restrict__ b_ih, const float* __restrict__ b_hh) {
    int idx = blockIdx.x * 256 + threadIdx.x;
    if (idx < N4D) {
        int d = idx >> 2, g = idx & 3;
        g_gb[idx] = b_ih[g * DN + d] + b_hh[g * DN + d];
    }
    if (idx >= KA * NF) return;
    int k = idx / NF, n = idx - k * NF;
    float v;
    if (n < N4D) {
        int d = n >> 2, g = n & 3;
        int gr = g * DN + d;
        v = (k < DN) ? W_hh[(size_t)gr * DN + k] : W_ih[(size_t)gr * INN + (k - DN)];
    } else if (n < N4D + DN) {
        int d = n - N4D;
        v = (k < DN) ? W_wp[(size_t)d * DN + k] : 0.f;
    } else {
        int e = n - N4D - DN;
        v = (k < DN) ? W_wa[(size_t)k * EN + e] : 0.f;
    }
    g_WfT[idx] = __float2half(v);
}
__global__ void pack_wi(const float* __restrict__ W_init_h, const float* __restrict__ W_init_c) {
    int idx = blockIdx.x * 256 + threadIdx.x;
    if (idx >= 288 * 1024) return;
    int k = idx / 1024, n = idx - k * 1024;
    float v = (n < DN) ? W_init_h[(size_t)n * 288 + k] : W_init_c[(size_t)(n - DN) * 288 + k];
    g_WiT[idx] = __float2half(v);
}
__global__ void enc_convert(const float* __restrict__ src) {
    size_t i = (size_t)blockIdx.x * 256 + threadIdx.x;
    const size_t n4 = (size_t)BATCH * SN * EN / 4;
    if (i >= n4) return;
    float4 v = ((const float4*)src)[i];
    __half2* dst = (__half2*)g_enc;
    dst[2 * i]     = __floats2half2_rn(v.x, v.y);
    dst[2 * i + 1] = __floats2half2_rn(v.z, v.w);
}
__global__ void seq_build(const float* __restrict__ hist, const float* __restrict__ cur) {
    int idx = blockIdx.x * 256 + threadIdx.x;
    if (idx >= BATCH * SEQLEN) return;
    int b = idx / SEQLEN, j = idx - b * SEQLEN;
    float v = (j < 31) ? hist[(size_t)b * 31 + j]
            : (j < 95) ? cur[(size_t)b * TN + (j - 31)] : 0.f;
    g_seq[idx] = v;
}
__global__ void mean_inp(const float* __restrict__ cEnc) {
    int b = blockIdx.x, tid = threadIdx.x;
    const float* p = cEnc + (size_t)b * SN * EN + tid;
    float s = 0.f;
#pragma unroll 8
    for (int i = 0; i < SN; i++) s += p[(size_t)i * EN];
    g_Inp[(size_t)b * 288 + tid] = __float2half(s * (1.f / 64.f));
    if (tid < INN)
        g_Inp[(size_t)b * 288 + EN + tid] = __float2half(g_seq[(size_t)b * SEQLEN + tid]);
}
__global__ void init_finish(const float* __restrict__ b_init_h, const float* __restrict__ b_init_c) {
    int idx = blockIdx.x * 256 + threadIdx.x;
    if (idx >= BATCH * KA) return;
    int b = idx / KA, d = idx - b * KA;
    if (d < DN) {
        float h0 = g_gates[(size_t)b * 1024 + d] + b_init_h[d];
        float c0 = g_gates[(size_t)b * 1024 + DN + d] + b_init_c[d];
        g_c[(size_t)b * DN + d] = c0;
        g_Xcat[0][idx] = __float2half(h0);
    } else {
        g_Xcat[0][idx] = __float2half(g_seq[(size_t)b * SEQLEN + (d - DN)]);  // x_0
    }
}

// ---------------- per-step attention / alignment / prediction ----------------
__global__ __launch_bounds__(256) void attn_step(const float* __restrict__ b_wp,
                                                 const float* __restrict__ W_vp,
                                                 const float* __restrict__ b_vp,
                                                 const float* __restrict__ W_fc,
                                                 const float* __restrict__ b_fc,
                                                 float* __restrict__ outPred,
                                                 float* __restrict__ outAlpha, int t) {
    const int b = blockIdx.x, tid = threadIdx.x;
    __shared__ __align__(16) __half sEnc[SN * EN2];   // padded rows: att conflict-free
    __shared__ float sU[EN];
    __shared__ float sAtt[SN];
    __shared__ float sAlpha[SN];
    __shared__ float sRed[8];
    __shared__ float sAligned;

    // encoder tile -> smem (row-padded). 256 halfs/row = 32 x 16B chunks per row.
    const uint4* ge = (const uint4*)(g_enc + (size_t)b * SN * EN);
#pragma unroll
    for (int i = 0; i < 8; i++) {
        int c = tid + i * 256;           // 16B chunk index, 0..2047
        int row = c >> 5, jc = c & 31;   // FIX: 32 chunks per 256-half row
        *(uint4*)(sEnc + row * EN2 + jc * 8) = ge[c];
    }

    sU[tid] = g_Pout[(size_t)b * NB + DN + tid];  // u_e

    // aligned = S * sigmoid( sum_d tanh(p_d + b_wp_d) * W_vp_d + b_vp )
    float part = 0.f;
#pragma unroll
    for (int it = 0; it < 2; it++) {
        int d = tid + it * 256;
        part += tanhf(g_Pout[(size_t)b * NB + d] + b_wp[d]) * W_vp[d];
    }
#pragma unroll
    for (int o = 16; o; o >>= 1) part += __shfl_xor_sync(0xffffffffu, part, o);
    if ((tid & 31) == 0) sRed[tid >> 5] = part;
    __syncthreads();
    if (tid == 0) {
        float tot = 0.f;
#pragma unroll
        for (int i = 0; i < 8; i++) tot += sRed[i];
        tot += b_vp[0];
        sAligned = (float)SN / (1.f + expf(-tot));
    }
    __syncthreads();
    const float aligned = sAligned;

    // att_s = <enc_s, u> : quad of threads per s (conflict-free via padding)
    {
        int s = tid >> 2, q = tid & 3;
        const __half* er = sEnc + s * EN2;
        float a = 0.f;
#pragma unroll 16
        for (int e = q; e < EN; e += 4) a += __half2float(er[e]) * sU[e];
        a += __shfl_xor_sync(0xffffffffu, a, 1);
        a += __shfl_xor_sync(0xffffffffu, a, 2);
        if (q == 0) sAtt[s] = a;
    }
    __syncthreads();

    // softmax over S=64 + Gaussian window (warp 0)
    if (tid < 32) {
        float a0 = sAtt[tid], a1 = sAtt[tid + 32];
        float m = fmaxf(a0, a1);
#pragma unroll
        for (int o = 16; o; o >>= 1) m = fmaxf(m, __shfl_xor_sync(0xffffffffu, m, o));
        float e0 = expf(a0 - m), e1 = expf(a1 - m);
        float s2 = e0 + e1;
#pragma unroll
        for (int o = 16; o; o >>= 1) s2 += __shfl_xor_sync(0xffffffffu, s2, o);
        float inv = 1.f / s2;
        float d0 = (float)tid - aligned, d1 = (float)(tid + 32) - aligned;
        sAlpha[tid]      = e0 * inv * expf(-0.5f * d0 * d0);
        sAlpha[tid + 32] = e1 * inv * expf(-0.5f * d1 * d1);
    }
    __syncthreads();

    if (tid < SN)
        outAlpha[((size_t)b * TN + t) * SN + tid] = sAlpha[tid];

    // awe_e = sum_s enc[s,e]*alpha_s ; pred = [awe | h2] @ W_fc + b_fc
    float awe = 0.f;
#pragma unroll 16
    for (int s = 0; s < SN; s++) awe += __half2float(sEnc[s * EN2 + tid]) * sAlpha[s];

    const float* hrow = g_H[t & 1] + (size_t)b * DN;
    float pp = awe * W_fc[tid]
             + hrow[tid]       * W_fc[EN + tid]
             + hrow[tid + 256] * W_fc[EN + 256 + tid];
#pragma unroll
    for (int o = 16; o; o >>= 1) pp += __shfl_xor_sync(0xffffffffu, pp, o);
    if ((tid & 31) == 0) sRed[tid >> 5] = pp;
    __syncthreads();
    if (tid == 0) {
        float tot = 0.f;
#pragma unroll
        for (int i = 0; i < 8; i++) tot += sRed[i];
        outPred[(size_t)b * TN + t] = tot + b_fc[0];
    }
}

// ---------------- launcher ----------------
extern "C" void kernel_launch(void* const* d_in, const int* in_sizes, int n_in,
                              void* d_out, int out_size) {
    const float* cEnc       = (const float*)d_in[0];
    const float* curSpeeds  = (const float*)d_in[1];
    const float* histSpeeds = (const float*)d_in[2];
    int wo = (n_in > 5 && in_sizes[5] == 1) ? 6 : 5;
    const float* W_init_h = (const float*)d_in[wo + 0];
    const float* b_init_h = (const float*)d_in[wo + 1];
    const float* W_init_c = (const float*)d_in[wo + 2];
    const float* b_init_c = (const float*)d_in[wo + 3];
    const float* W_ih     = (const float*)d_in[wo + 4];
    const float* W_hh     = (const float*)d_in[wo + 5];
    const float* b_ih     = (const float*)d_in[wo + 6];
    const float* b_hh     = (const float*)d_in[wo + 7];
    const float* W_wa     = (const float*)d_in[wo + 8];
    // b_wa (wo+9) is softmax-invariant: unused
    const float* W_wp     = (const float*)d_in[wo + 10];
    const float* b_wp     = (const float*)d_in[wo + 11];
    const float* W_vp     = (const float*)d_in[wo + 12];
    const float* b_vp     = (const float*)d_in[wo + 13];
    const float* W_fc     = (const float*)d_in[wo + 14];
    const float* b_fc     = (const float*)d_in[wo + 15];

    float* outPred  = (float*)d_out;                 // [B,T,1]
    float* outAlpha = outPred + (size_t)BATCH * TN;  // [B,T,S]

    enc_convert<<<32768, 256>>>(cEnc);
    seq_build<<<(BATCH * SEQLEN) / 256, 256>>>(histSpeeds, curSpeeds);
    pack_wf<<<(KA * NF + 255) / 256, 256>>>(W_hh, W_ih, W_wp, W_wa, b_ih, b_hh);
    pack_wi<<<(288 * 1024) / 256, 256>>>(W_init_h, W_init_c);
    mean_inp<<<BATCH, 256>>>(cEnc);
    gemmI_kernel<<<dim3(1024 / BN, BATCH / BM), 256>>>();
    init_finish<<<(BATCH * KA) / 256, 256>>>(b_init_h, b_init_c);

    // pipelined: fused_step(t) -> gates_t (+LSTM) and pu of h_{t-1};
    // attn(t-1) consumes that pu and H_{t-1}. fused_step(TN) is the pu-only tail.
    for (int t = 0; t <= TN; t++) {
        fused_step<<<dim3(NF / BN, BATCH / BM), 256>>>(t);
        if (t >= 1)
            attn_step<<<BATCH, 256>>>(b_wp, W_vp, b_vp, W_fc, b_fc,
                                      outPred, outAlpha, t - 1);
    }
}

// round 7
// speedup vs baseline: 1.5735x; 1.2833x over previous
#include <cuda_runtime.h>
#include <cuda_fp16.h>
#include <cstdint>
#include <cstddef>

#define BATCH 2048
#define SN 64         // S
#define EN 256        // E
#define EN2 264       // padded smem row (conflict-free att)
#define DN 512        // D
#define INN 32        // IN
#define TN 64         // T
#define KA 544        // D + IN
#define N4D 2048      // 4*D (gate cols, interleaved n=4d+g)
#define NF 2816       // fused cols: 2048 gates | 512 p | 256 u
#define NB 768        // p|u rows in g_Pout
#define SEQLEN 128    // 31 hist + 64 cur + pad

#define BM 128
#define BN 128
#define BK 32
// 3-stage pipeline smem: 3*(128*40 + 32*136) halves = 56832 bytes
#define DYN_SMEM (3 * ((BM * (BK + 8)) + (BK * (BN + 8))) * 2)

// ---------------- scratch (__device__ globals; no allocation) ----------------
__device__ __align__(16) __half g_enc[(size_t)BATCH * SN * EN];    // fp16 encoder
__device__ __align__(16) __half g_Xcat[2][(size_t)BATCH * KA];     // [h fp16 | x fp16], double buf
__device__ __align__(16) float  g_c[(size_t)BATCH * DN];           // LSTM cell state
__device__ __align__(16) float  g_gates[(size_t)BATCH * N4D];      // init GEMM output only
__device__ __align__(16) float  g_Pout[(size_t)BATCH * NB];        // p,u fp32
__device__ __align__(16) __half g_WfT[(size_t)KA * NF];            // fused weights [K][N]
__device__ __align__(16) __half g_WiT[(size_t)288 * 1024];         // init weights [K][N]
__device__ __align__(16) __half g_Inp[(size_t)BATCH * 288];        // [mean_enc | speed0]
__device__ __align__(16) float  g_gb[N4D];                         // (b_ih+b_hh) interleaved 4d+g
__device__ __align__(16) float  g_seq[(size_t)BATCH * SEQLEN];     // speed sequence
__device__ int g_cnt[16];                                          // pu completion counters

// ---------------- helpers ----------------
__device__ __forceinline__ uint32_t smem_u32(const void* p) {
    return (uint32_t)__cvta_generic_to_shared(p);
}
__device__ __forceinline__ void cp16(uint32_t dst, const void* src) {
    asm volatile("cp.async.cg.shared.global [%0], [%1], 16;\n" :: "r"(dst), "l"(src));
}

// ---------------- fp16 TC GEMM mainloop: acc += A[M,K] * Bt[K,N] ----------------
// 3-stage cp.async pipeline in dynamic smem. NOTE: no trailing __syncthreads —
// caller must sync before reusing dynsmem.
template<int K, int LDA, int LDB>
__device__ __forceinline__ void gemm_mainloop(const __half* __restrict__ A,
                                              const __half* __restrict__ Bt,
                                              int bm, int bn,
                                              float acc[4][4][4],
                                              char* dynsmem)
{
    auto As = (__half (*)[BM][BK + 8])dynsmem;
    auto Bs = (__half (*)[BK][BN + 8])(dynsmem + 3 * BM * (BK + 8) * 2);

    const int tid  = threadIdx.x;
    const int lane = tid & 31;
    const int warp = tid >> 5;
    const int wm   = warp & 1;
    const int wn   = warp >> 1;

#pragma unroll
    for (int a = 0; a < 4; a++)
#pragma unroll
        for (int b = 0; b < 4; b++)
#pragma unroll
            for (int c = 0; c < 4; c++) acc[a][b][c] = 0.f;

    const int am  = tid >> 2;
    const int akq = tid & 3;
    const int bk  = tid >> 4;
    const int bnq = tid & 15;

    auto load_async = [&](int kt, int buf) {
        const int k0 = kt * BK;
        cp16(smem_u32(&As[buf][am][akq * 8]),
             A + (size_t)(bm + am) * LDA + k0 + akq * 8);
        cp16(smem_u32(&As[buf][am + 64][akq * 8]),
             A + (size_t)(bm + am + 64) * LDA + k0 + akq * 8);
        cp16(smem_u32(&Bs[buf][bk][bnq * 8]),
             Bt + (size_t)(k0 + bk) * LDB + bn + bnq * 8);
        cp16(smem_u32(&Bs[buf][bk + 16][bnq * 8]),
             Bt + (size_t)(k0 + bk + 16) * LDB + bn + bnq * 8);
        asm volatile("cp.async.commit_group;\n");
    };

    constexpr int KT = K / BK;
    load_async(0, 0);
    load_async(1, 1);

    for (int kt = 0; kt < KT; kt++) {
        if (kt + 1 < KT) asm volatile("cp.async.wait_group 1;\n");
        else             asm volatile("cp.async.wait_group 0;\n");
        __syncthreads();
        if (kt + 2 < KT) load_async(kt + 2, (kt + 2) % 3);
        const int buf = kt % 3;

#pragma unroll
        for (int kk = 0; kk < 2; kk++) {
            uint32_t af[4][4], bf[4][2];
#pragma unroll
            for (int im = 0; im < 4; im++) {
                uint32_t addr = smem_u32(
                    &As[buf][wm * 64 + im * 16 + (lane & 15)][kk * 16 + (lane >> 4) * 8]);
                asm volatile("ldmatrix.sync.aligned.m8n8.x4.shared.b16 {%0,%1,%2,%3}, [%4];\n"
                             : "=r"(af[im][0]), "=r"(af[im][1]), "=r"(af[im][2]), "=r"(af[im][3])
                             : "r"(addr));
            }
#pragma unroll
            for (int in = 0; in < 4; in++) {
                uint32_t addr = smem_u32(&Bs[buf][kk * 16 + (lane & 15)][wn * 32 + in * 8]);
                asm volatile("ldmatrix.sync.aligned.m8n8.x2.trans.shared.b16 {%0,%1}, [%2];\n"
                             : "=r"(bf[in][0]), "=r"(bf[in][1])
                             : "r"(addr));
            }
#pragma unroll
            for (int im = 0; im < 4; im++)
#pragma unroll
                for (int in = 0; in < 4; in++)
                    asm volatile("mma.sync.aligned.m16n8k16.row.col.f32.f16.f16.f32 "
                                 "{%0,%1,%2,%3}, {%4,%5,%6,%7}, {%8,%9}, {%0,%1,%2,%3};\n"
                                 : "+f"(acc[im][in][0]), "+f"(acc[im][in][1]),
                                   "+f"(acc[im][in][2]), "+f"(acc[im][in][3])
                                 : "r"(af[im][0]), "r"(af[im][1]), "r"(af[im][2]), "r"(af[im][3]),
                                   "r"(bf[in][0]), "r"(bf[in][1]));
        }
        __syncthreads();
    }
}

// ---------------- fused per-step kernel ----------------
// Grid (1D, 2400 blocks), dispatch order guarantees producers first:
//   blk [0,96)    : pu GEMM tiles (cols 2048..2815) -> g_Pout, then counter arrive
//   blk [96,352)  : gate GEMM tiles (cols 0..2047)  -> LSTM epilogue -> Xcat/c
//   blk [352,2400): attention CTAs for step t-1 (spin on counters; skip at t==0)
__global__ __launch_bounds__(256, 2) void fused_step(
    int t,
    const float* __restrict__ b_wp, const float* __restrict__ W_vp,
    const float* __restrict__ b_vp, const float* __restrict__ W_fc,
    const float* __restrict__ b_fc,
    float* __restrict__ outPred, float* __restrict__ outAlpha)
{
    extern __shared__ char dynsmem[];
    const int blk = blockIdx.x;
    const int tid = threadIdx.x;

    if (blk < 352) {
        // ================= GEMM tiles =================
        if (blk >= 96 && t == TN) return;   // no gates needed on the pu-only tail
        int bx, by;
        if (blk < 96) { by = blk / 6; bx = 16 + blk % 6; }
        else          { int g = blk - 96; by = g >> 4; bx = g & 15; }
        const int bm = by * BM;
        const int bn = bx * BN;

        const __half* Ain = g_Xcat[t & 1];
        __half* Xout      = g_Xcat[(t + 1) & 1];

        float acc[4][4][4];
        gemm_mainloop<KA, KA, NF>(Ain, g_WfT, bm, bn, acc, dynsmem);

        const int lane = tid & 31;
        const int warp = tid >> 5;
        const int wm   = warp & 1;
        const int wn   = warp >> 1;

        if (bn < N4D) {
            // ---- LSTM epilogue, staged through smem for coalesced gmem ----
            float*  sC = (float*)dynsmem;                     // [128][36] c in/out
            __half* sH = (__half*)(dynsmem + 128 * 36 * 4);   // [128][40] h2
            const int d0 = bn >> 2;                           // 32 consecutive d

            __syncthreads();   // mainloop done; reuse smem
            // phase 1: coalesced c tile load
#pragma unroll
            for (int k = 0; k < 4; k++) {
                int idx = tid + k * 256;          // 0..1023 float4 chunks
                int row = idx >> 3, q = idx & 7;
                ((float4*)sC)[row * 9 + q] =
                    *(const float4*)(g_c + (size_t)(bm + row) * DN + d0 + q * 4);
            }
            __syncthreads();

            // phase 2: gates -> (c2, h2) into smem
            const int pair_sel = lane & 1;
#pragma unroll
            for (int im = 0; im < 4; im++) {
                const int rl = wm * 64 + im * 16 + (lane >> 2);
#pragma unroll
                for (int in = 0; in < 4; in++) {
                    const int ccg = bn + wn * 32 + in * 8 + (lane & 3) * 2;
                    float b0 = __ldg(&g_gb[ccg]);
                    float b1 = __ldg(&g_gb[ccg + 1]);
                    float a0 = acc[im][in][0] + b0;
                    float a1 = acc[im][in][1] + b1;
                    float a2 = acc[im][in][2] + b0;
                    float a3 = acc[im][in][3] + b1;
                    float o0 = __shfl_xor_sync(0xffffffffu, a0, 1);
                    float o1 = __shfl_xor_sync(0xffffffffu, a1, 1);
                    float o2 = __shfl_xor_sync(0xffffffffu, a2, 1);
                    float o3 = __shfl_xor_sync(0xffffffffu, a3, 1);
                    int row_l; float xi, xf, xg, xo;
                    if (pair_sel == 0) { row_l = rl;     xi = a0; xf = a1; xg = o0; xo = o1; }
                    else               { row_l = rl + 8; xi = o2; xf = o3; xg = a2; xo = a3; }
                    const int d_l = wn * 8 + in * 2 + ((lane & 3) >> 1);
                    float si = 1.f / (1.f + expf(-xi));
                    float sf = 1.f / (1.f + expf(-xf));
                    float so = 1.f / (1.f + expf(-xo));
                    float c2 = sf * sC[row_l * 36 + d_l] + si * tanhf(xg);
                    float h2 = so * tanhf(c2);
                    sC[row_l * 36 + d_l] = c2;
                    sH[row_l * 40 + d_l] = __float2half(h2);
                }
            }
            __syncthreads();

            // phase 3: coalesced stores (c float4, h uint4=8 halves)
#pragma unroll
            for (int k = 0; k < 4; k++) {
                int idx = tid + k * 256;
                int row = idx >> 3, q = idx & 7;
                *(float4*)(g_c + (size_t)(bm + row) * DN + d0 + q * 4) =
                    ((const float4*)sC)[row * 9 + q];
            }
#pragma unroll
            for (int k = 0; k < 2; k++) {
                int idx = tid + k * 256;          // 0..511 uint4 chunks
                int row = idx >> 2, q = idx & 3;
                *(uint4*)(Xout + (size_t)(bm + row) * KA + d0 + q * 8) =
                    ((const uint4*)sH)[row * 5 + q];
            }
        } else {
            // ---- pu store + counter arrive ----
#pragma unroll
            for (int im = 0; im < 4; im++) {
                const int r = bm + wm * 64 + im * 16 + (lane >> 2);
#pragma unroll
                for (int in = 0; in < 4; in++) {
                    const int cc = bn - N4D + wn * 32 + in * 8 + (lane & 3) * 2;
                    *(float2*)(g_Pout + (size_t)r * NB + cc) =
                        make_float2(acc[im][in][0], acc[im][in][1]);
                    *(float2*)(g_Pout + (size_t)(r + 8) * NB + cc) =
                        make_float2(acc[im][in][2], acc[im][in][3]);
                }
            }
            // first pu block per band writes x_{t+1} into Xout
            if (bx == 16) {
                const int rrow = bm + (tid >> 1);
                const int jb = (tid & 1) * 16;
#pragma unroll
                for (int j = 0; j < 16; j++) {
                    int jj = jb + j;
                    Xout[(size_t)rrow * KA + DN + jj] =
                        __float2half(g_seq[(size_t)rrow * SEQLEN + t + 1 + jj]);
                }
            }
            __threadfence();
            __syncthreads();
            if (tid == 0) atomicAdd(&g_cnt[by], 1);
        }
        return;
    }

    // ================= attention CTAs (step t-1) =================
    if (t == 0) return;
    const int b  = blk - 352;
    const int tt = t - 1;

    __half* sEnc = (__half*)dynsmem;                         // [64][264]
    float*  sF   = (float*)(dynsmem + SN * EN2 * 2);
    float*  sU      = sF;           // 256
    float*  sAtt    = sF + 256;     // 64
    float*  sAlpha  = sF + 320;     // 64
    float*  sRed    = sF + 384;     // 8
    float*  sAligned= sF + 392;     // 1

    // preload encoder tile while waiting on pu producers
    const uint4* ge = (const uint4*)(g_enc + (size_t)b * SN * EN);
#pragma unroll
    for (int i = 0; i < 8; i++) {
        int c = tid + i * 256;                 // 0..2047 16B chunks
        int row = c >> 5, jc = c & 31;
        cp16(smem_u32(sEnc + row * EN2 + jc * 8), ge + c);
    }
    asm volatile("cp.async.commit_group;\n");

    if (tid == 0) {
        const int band = b >> 7;
        const int target = 6 * (t + 1);
        while (*(volatile int*)&g_cnt[band] < target) __nanosleep(64);
        __threadfence();
    }
    __syncthreads();                           // pu data now visible to all
    asm volatile("cp.async.wait_group 0;\n");

    sU[tid] = g_Pout[(size_t)b * NB + DN + tid];   // u_e

    // aligned = S * sigmoid( sum_d tanh(p_d + b_wp_d) * W_vp_d + b_vp )
    float part = 0.f;
#pragma unroll
    for (int it = 0; it < 2; it++) {
        int d = tid + it * 256;
        part += tanhf(g_Pout[(size_t)b * NB + d] + b_wp[d]) * W_vp[d];
    }
#pragma unroll
    for (int o = 16; o; o >>= 1) part += __shfl_xor_sync(0xffffffffu, part, o);
    if ((tid & 31) == 0) sRed[tid >> 5] = part;
    __syncthreads();
    if (tid == 0) {
        float tot = 0.f;
#pragma unroll
        for (int i = 0; i < 8; i++) tot += sRed[i];
        tot += b_vp[0];
        sAligned[0] = (float)SN / (1.f + expf(-tot));
    }
    __syncthreads();
    const float aligned = sAligned[0];

    // att_s = <enc_s, u>
    {
        int s = tid >> 2, q = tid & 3;
        const __half* er = sEnc + s * EN2;
        float a = 0.f;
#pragma unroll 16
        for (int e = q; e < EN; e += 4) a += __half2float(er[e]) * sU[e];
        a += __shfl_xor_sync(0xffffffffu, a, 1);
        a += __shfl_xor_sync(0xffffffffu, a, 2);
        if (q == 0) sAtt[s] = a;
    }
    __syncthreads();

    // softmax + Gaussian window (warp 0)
    if (tid < 32) {
        float a0 = sAtt[tid], a1 = sAtt[tid + 32];
        float m = fmaxf(a0, a1);
#pragma unroll
        for (int o = 16; o; o >>= 1) m = fmaxf(m, __shfl_xor_sync(0xffffffffu, m, o));
        float e0 = expf(a0 - m), e1 = expf(a1 - m);
        float s2 = e0 + e1;
#pragma unroll
        for (int o = 16; o; o >>= 1) s2 += __shfl_xor_sync(0xffffffffu, s2, o);
        float inv = 1.f / s2;
        float d0 = (float)tid - aligned, d1 = (float)(tid + 32) - aligned;
        sAlpha[tid]      = e0 * inv * expf(-0.5f * d0 * d0);
        sAlpha[tid + 32] = e1 * inv * expf(-0.5f * d1 * d1);
    }
    __syncthreads();

    if (tid < SN)
        outAlpha[((size_t)b * TN + tt) * SN + tid] = sAlpha[tid];

    // awe + pred (h read as fp16 from Xcat[t&1] = h_{t-1})
    float awe = 0.f;
#pragma unroll 16
    for (int s = 0; s < SN; s++) awe += __half2float(sEnc[s * EN2 + tid]) * sAlpha[s];

    const __half* hrow = g_Xcat[t & 1] + (size_t)b * KA;
    float pp = awe * W_fc[tid]
             + __half2float(hrow[tid])       * W_fc[EN + tid]
             + __half2float(hrow[tid + 256]) * W_fc[EN + 256 + tid];
#pragma unroll
    for (int o = 16; o; o >>= 1) pp += __shfl_xor_sync(0xffffffffu, pp, o);
    if ((tid & 31) == 0) sRed[tid >> 5] = pp;
    __syncthreads();
    if (tid == 0) {
        float tot = 0.f;
#pragma unroll
        for (int i = 0; i < 8; i++) tot += sRed[i];
        outPred[(size_t)b * TN + tt] = tot + b_fc[0];
    }
}

// ---------------- init GEMM (h0|c0) ----------------
__global__ __launch_bounds__(256, 2) void gemmI_kernel() {
    extern __shared__ char dynsmem[];
    float acc[4][4][4];
    const int bm = blockIdx.y * BM;
    const int bn = blockIdx.x * BN;
    gemm_mainloop<288, 288, 1024>(g_Inp, g_WiT, bm, bn, acc, dynsmem);
    const int tid  = threadIdx.x;
    const int lane = tid & 31;
    const int warp = tid >> 5;
    const int wm   = warp & 1;
    const int wn   = warp >> 1;
#pragma unroll
    for (int im = 0; im < 4; im++) {
        const int r = bm + wm * 64 + im * 16 + (lane >> 2);
#pragma unroll
        for (int in = 0; in < 4; in++) {
            const int cc = bn + wn * 32 + in * 8 + (lane & 3) * 2;
            *(float2*)(g_gates + (size_t)r * 1024 + cc) =
                make_float2(acc[im][in][0], acc[im][in][1]);
            *(float2*)(g_gates + (size_t)(r + 8) * 1024 + cc) =
                make_float2(acc[im][in][2], acc[im][in][3]);
        }
    }
}

// ---------------- init / pack kernels ----------------
__global__ void pack_wf(const float* __restrict__ W_hh, const float* __restrict__ W_ih,
                        const float* __restrict__ W_wp, const float* __restrict__ W_wa,
                        const float* __restrict__ b_ih, const float* __restrict__ b_hh) {
    int idx = blockIdx.x * 256 + threadIdx.x;
    if (idx < N4D) {
        int d = idx >> 2, g = idx & 3;
        g_gb[idx] = b_ih[g * DN + d] + b_hh[g * DN + d];
    }
    if (idx >= KA * NF) return;
    int k = idx / NF, n = idx - k * NF;
    float v;
    if (n < N4D) {
        int d = n >> 2, g = n & 3;
        int gr = g * DN + d;
        v = (k < DN) ? W_hh[(size_t)gr * DN + k] : W_ih[(size_t)gr * INN + (k - DN)];
    } else if (n < N4D + DN) {
        int d = n - N4D;
        v = (k < DN) ? W_wp[(size_t)d * DN + k] : 0.f;
    } else {
        int e = n - N4D - DN;
        v = (k < DN) ? W_wa[(size_t)k * EN + e] : 0.f;
    }
    g_WfT[idx] = __float2half(v);
}
__global__ void pack_wi(const float* __restrict__ W_init_h, const float* __restrict__ W_init_c) {
    int idx = blockIdx.x * 256 + threadIdx.x;
    if (idx >= 288 * 1024) return;
    int k = idx / 1024, n = idx - k * 1024;
    float v = (n < DN) ? W_init_h[(size_t)n * 288 + k] : W_init_c[(size_t)(n - DN) * 288 + k];
    g_WiT[idx] = __float2half(v);
}
__global__ void enc_convert(const float* __restrict__ src) {
    size_t i = (size_t)blockIdx.x * 256 + threadIdx.x;
    const size_t n4 = (size_t)BATCH * SN * EN / 4;
    if (i >= n4) return;
    float4 v = ((const float4*)src)[i];
    __half2* dst = (__half2*)g_enc;
    dst[2 * i]     = __floats2half2_rn(v.x, v.y);
    dst[2 * i + 1] = __floats2half2_rn(v.z, v.w);
}
__global__ void seq_build(const float* __restrict__ hist, const float* __restrict__ cur) {
    int idx = blockIdx.x * 256 + threadIdx.x;
    if (idx < 16) g_cnt[idx] = 0;   // reset producer counters each run
    if (idx >= BATCH * SEQLEN) return;
    int b = idx / SEQLEN, j = idx - b * SEQLEN;
    float v = (j < 31) ? hist[(size_t)b * 31 + j]
            : (j < 95) ? cur[(size_t)b * TN + (j - 31)] : 0.f;
    g_seq[idx] = v;
}
__global__ void mean_inp(const float* __restrict__ cEnc) {
    int b = blockIdx.x, tid = threadIdx.x;
    const float* p = cEnc + (size_t)b * SN * EN + tid;
    float s = 0.f;
#pragma unroll 8
    for (int i = 0; i < SN; i++) s += p[(size_t)i * EN];
    g_Inp[(size_t)b * 288 + tid] = __float2half(s * (1.f / 64.f));
    if (tid < INN)
        g_Inp[(size_t)b * 288 + EN + tid] = __float2half(g_seq[(size_t)b * SEQLEN + tid]);
}
__global__ void init_finish(const float* __restrict__ b_init_h, const float* __restrict__ b_init_c) {
    int idx = blockIdx.x * 256 + threadIdx.x;
    if (idx >= BATCH * KA) return;
    int b = idx / KA, d = idx - b * KA;
    if (d < DN) {
        float h0 = g_gates[(size_t)b * 1024 + d] + b_init_h[d];
        float c0 = g_gates[(size_t)b * 1024 + DN + d] + b_init_c[d];
        g_c[(size_t)b * DN + d] = c0;
        g_Xcat[0][idx] = __float2half(h0);
    } else {
        g_Xcat[0][idx] = __float2half(g_seq[(size_t)b * SEQLEN + (d - DN)]);  // x_0
    }
}

// ---------------- launcher ----------------
extern "C" void kernel_launch(void* const* d_in, const int* in_sizes, int n_in,
                              void* d_out, int out_size) {
    const float* cEnc       = (const float*)d_in[0];
    const float* curSpeeds  = (const float*)d_in[1];
    const float* histSpeeds = (const float*)d_in[2];
    int wo = (n_in > 5 && in_sizes[5] == 1) ? 6 : 5;
    const float* W_init_h = (const float*)d_in[wo + 0];
    const float* b_init_h = (const float*)d_in[wo + 1];
    const float* W_init_c = (const float*)d_in[wo + 2];
    const float* b_init_c = (const float*)d_in[wo + 3];
    const float* W_ih     = (const float*)d_in[wo + 4];
    const float* W_hh     = (const float*)d_in[wo + 5];
    const float* b_ih     = (const float*)d_in[wo + 6];
    const float* b_hh     = (const float*)d_in[wo + 7];
    const float* W_wa     = (const float*)d_in[wo + 8];
    // b_wa (wo+9) is softmax-invariant: unused
    const float* W_wp     = (const float*)d_in[wo + 10];
    const float* b_wp     = (const float*)d_in[wo + 11];
    const float* W_vp     = (const float*)d_in[wo + 12];
    const float* b_vp     = (const float*)d_in[wo + 13];
    const float* W_fc     = (const float*)d_in[wo + 14];
    const float* b_fc     = (const float*)d_in[wo + 15];

    float* outPred  = (float*)d_out;                 // [B,T,1]
    float* outAlpha = outPred + (size_t)BATCH * TN;  // [B,T,S]

    cudaFuncSetAttribute(fused_step, cudaFuncAttributeMaxDynamicSharedMemorySize, DYN_SMEM);
    cudaFuncSetAttribute(gemmI_kernel, cudaFuncAttributeMaxDynamicSharedMemorySize, DYN_SMEM);

    enc_convert<<<32768, 256>>>(cEnc);
    seq_build<<<(BATCH * SEQLEN) / 256, 256>>>(histSpeeds, curSpeeds);
    pack_wf<<<(KA * NF + 255) / 256, 256>>>(W_hh, W_ih, W_wp, W_wa, b_ih, b_hh);
    pack_wi<<<(288 * 1024) / 256, 256>>>(W_init_h, W_init_c);
    mean_inp<<<BATCH, 256>>>(cEnc);
    gemmI_kernel<<<dim3(1024 / BN, BATCH / BM), 256, DYN_SMEM>>>();
    init_finish<<<(BATCH * KA) / 256, 256>>>(b_init_h, b_init_c);

    // fused: launch t computes gates_t (+LSTM) and pu of h_{t-1}; its attn CTAs
    // consume pu + h_{t-1} in the same launch. t=TN is the pu+attn tail.
    for (int t = 0; t <= TN; t++) {
        fused_step<<<352 + BATCH, 256, DYN_SMEM>>>(t, b_wp, W_vp, b_vp, W_fc, b_fc,
                                                   outPred, outAlpha);
    }
}

// round 8
// speedup vs baseline: 1.7480x; 1.1110x over previous
#include <cuda_runtime.h>
#include <cuda_fp16.h>
#include <cstdint>
#include <cstddef>

#define BATCH 2048
#define SN 64         // S
#define EN 256        // E
#define EN2 264       // padded smem row (conflict-free att)
#define DN 512        // D
#define INN 32        // IN
#define TN 64         // T
#define KA 544        // D + IN
#define N4D 2048      // 4*D (gate cols, interleaved n=4d+g)
#define NF 2816       // fused cols: 2048 gates | 512 p | 256 u
#define NB 768        // p|u rows in g_Pout
#define SEQLEN 128    // 31 hist + 64 cur + pad

#define BM 128
#define BN 128
#define BK 32
// 3-stage pipeline smem: 3*(128*40 + 32*136) halves = 56832 bytes
#define DYN_SMEM (3 * ((BM * (BK + 8)) + (BK * (BN + 8))) * 2)

// ---------------- scratch (__device__ globals; no allocation) ----------------
__device__ __align__(16) __half g_enc[(size_t)BATCH * SN * EN];    // fp16 encoder
__device__ __align__(16) __half g_Xcat[3][(size_t)BATCH * KA];     // [h fp16 | x fp16], triple buf
__device__ __align__(16) float  g_c[(size_t)BATCH * DN];           // LSTM cell state
__device__ __align__(16) float  g_gates[(size_t)BATCH * N4D];      // init GEMM output only
__device__ __align__(16) float  g_Pout[2][(size_t)BATCH * NB];     // p,u fp32, double buf
__device__ __align__(16) __half g_WfT[(size_t)KA * NF];            // fused weights [K][N]
__device__ __align__(16) __half g_WiT[(size_t)288 * 1024];         // init weights [K][N]
__device__ __align__(16) __half g_Inp[(size_t)BATCH * 288];        // [mean_enc | speed0]
__device__ __align__(16) float  g_gb[N4D];                         // (b_ih+b_hh) interleaved 4d+g
__device__ __align__(16) float  g_seq[(size_t)BATCH * SEQLEN];     // speed sequence

// ---------------- helpers ----------------
__device__ __forceinline__ uint32_t smem_u32(const void* p) {
    return (uint32_t)__cvta_generic_to_shared(p);
}
__device__ __forceinline__ void cp16(uint32_t dst, const void* src) {
    asm volatile("cp.async.cg.shared.global [%0], [%1], 16;\n" :: "r"(dst), "l"(src));
}

// ---------------- fp16 TC GEMM mainloop: acc += A[M,K] * Bt[K,N] ----------------
// 3-stage cp.async pipeline in dynamic smem. NOTE: no trailing __syncthreads —
// caller must sync before reusing dynsmem.
template<int K, int LDA, int LDB>
__device__ __forceinline__ void gemm_mainloop(const __half* __restrict__ A,
                                              const __half* __restrict__ Bt,
                                              int bm, int bn,
                                              float acc[4][4][4],
                                              char* dynsmem)
{
    auto As = (__half (*)[BM][BK + 8])dynsmem;
    auto Bs = (__half (*)[BK][BN + 8])(dynsmem + 3 * BM * (BK + 8) * 2);

    const int tid  = threadIdx.x;
    const int lane = tid & 31;
    const int warp = tid >> 5;
    const int wm   = warp & 1;
    const int wn   = warp >> 1;

#pragma unroll
    for (int a = 0; a < 4; a++)
#pragma unroll
        for (int b = 0; b < 4; b++)
#pragma unroll
            for (int c = 0; c < 4; c++) acc[a][b][c] = 0.f;

    const int am  = tid >> 2;
    const int akq = tid & 3;
    const int bk  = tid >> 4;
    const int bnq = tid & 15;

    auto load_async = [&](int kt, int buf) {
        const int k0 = kt * BK;
        cp16(smem_u32(&As[buf][am][akq * 8]),
             A + (size_t)(bm + am) * LDA + k0 + akq * 8);
        cp16(smem_u32(&As[buf][am + 64][akq * 8]),
             A + (size_t)(bm + am + 64) * LDA + k0 + akq * 8);
        cp16(smem_u32(&Bs[buf][bk][bnq * 8]),
             Bt + (size_t)(k0 + bk) * LDB + bn + bnq * 8);
        cp16(smem_u32(&Bs[buf][bk + 16][bnq * 8]),
             Bt + (size_t)(k0 + bk + 16) * LDB + bn + bnq * 8);
        asm volatile("cp.async.commit_group;\n");
    };

    constexpr int KT = K / BK;
    load_async(0, 0);
    load_async(1, 1);

    for (int kt = 0; kt < KT; kt++) {
        if (kt + 1 < KT) asm volatile("cp.async.wait_group 1;\n");
        else             asm volatile("cp.async.wait_group 0;\n");
        __syncthreads();
        if (kt + 2 < KT) load_async(kt + 2, (kt + 2) % 3);
        const int buf = kt % 3;

#pragma unroll
        for (int kk = 0; kk < 2; kk++) {
            uint32_t af[4][4], bf[4][2];
#pragma unroll
            for (int im = 0; im < 4; im++) {
                uint32_t addr = smem_u32(
                    &As[buf][wm * 64 + im * 16 + (lane & 15)][kk * 16 + (lane >> 4) * 8]);
                asm volatile("ldmatrix.sync.aligned.m8n8.x4.shared.b16 {%0,%1,%2,%3}, [%4];\n"
                             : "=r"(af[im][0]), "=r"(af[im][1]), "=r"(af[im][2]), "=r"(af[im][3])
                             : "r"(addr));
            }
#pragma unroll
            for (int in = 0; in < 4; in++) {
                uint32_t addr = smem_u32(&Bs[buf][kk * 16 + (lane & 15)][wn * 32 + in * 8]);
                asm volatile("ldmatrix.sync.aligned.m8n8.x2.trans.shared.b16 {%0,%1}, [%2];\n"
                             : "=r"(bf[in][0]), "=r"(bf[in][1])
                             : "r"(addr));
            }
#pragma unroll
            for (int im = 0; im < 4; im++)
#pragma unroll
                for (int in = 0; in < 4; in++)
                    asm volatile("mma.sync.aligned.m16n8k16.row.col.f32.f16.f16.f32 "
                                 "{%0,%1,%2,%3}, {%4,%5,%6,%7}, {%8,%9}, {%0,%1,%2,%3};\n"
                                 : "+f"(acc[im][in][0]), "+f"(acc[im][in][1]),
                                   "+f"(acc[im][in][2]), "+f"(acc[im][in][3])
                                 : "r"(af[im][0]), "r"(af[im][1]), "r"(af[im][2]), "r"(af[im][3]),
                                   "r"(bf[in][0]), "r"(bf[in][1]));
        }
        __syncthreads();
    }
}

// ---------------- per-step GEMM kernel (352 CTAs) ----------------
// blk [0,96)   : pu tiles (cols 2048..2815) -> g_Pout[t&1]
// blk [96,352) : gate tiles (cols 0..2047)  -> LSTM epilogue -> Xcat[(t+1)%3], g_c
__global__ __launch_bounds__(256, 2) void fused_gemm(int t) {
    extern __shared__ char dynsmem[];
    const int blk = blockIdx.x;
    const int tid = threadIdx.x;

    if (blk >= 96 && t == TN) return;   // pu-only tail
    int bx, by;
    if (blk < 96) { by = blk / 6; bx = 16 + blk % 6; }
    else          { int g = blk - 96; by = g >> 4; bx = g & 15; }
    const int bm = by * BM;
    const int bn = bx * BN;

    const __half* Ain = g_Xcat[t % 3];
    __half* Xout      = g_Xcat[(t + 1) % 3];
    float*  PoutW     = g_Pout[t & 1];

    float acc[4][4][4];
    gemm_mainloop<KA, KA, NF>(Ain, g_WfT, bm, bn, acc, dynsmem);

    const int lane = tid & 31;
    const int warp = tid >> 5;
    const int wm   = warp & 1;
    const int wn   = warp >> 1;

    if (bn < N4D) {
        // ---- LSTM epilogue, staged through smem for coalesced gmem ----
        float*  sC = (float*)dynsmem;                     // [128][36] c in/out
        __half* sH = (__half*)(dynsmem + 128 * 36 * 4);   // [128][40] h2
        const int d0 = bn >> 2;                           // 32 consecutive d

        __syncthreads();   // mainloop done; reuse smem
        // phase 1: coalesced c tile load
#pragma unroll
        for (int k = 0; k < 4; k++) {
            int idx = tid + k * 256;          // 0..1023 float4 chunks
            int row = idx >> 3, q = idx & 7;
            ((float4*)sC)[row * 9 + q] =
                *(const float4*)(g_c + (size_t)(bm + row) * DN + d0 + q * 4);
        }
        __syncthreads();

        // phase 2: gates -> (c2, h2) into smem
        const int pair_sel = lane & 1;
#pragma unroll
        for (int im = 0; im < 4; im++) {
            const int rl = wm * 64 + im * 16 + (lane >> 2);
#pragma unroll
            for (int in = 0; in < 4; in++) {
                const int ccg = bn + wn * 32 + in * 8 + (lane & 3) * 2;
                float b0 = __ldg(&g_gb[ccg]);
                float b1 = __ldg(&g_gb[ccg + 1]);
                float a0 = acc[im][in][0] + b0;
                float a1 = acc[im][in][1] + b1;
                float a2 = acc[im][in][2] + b0;
                float a3 = acc[im][in][3] + b1;
                float o0 = __shfl_xor_sync(0xffffffffu, a0, 1);
                float o1 = __shfl_xor_sync(0xffffffffu, a1, 1);
                float o2 = __shfl_xor_sync(0xffffffffu, a2, 1);
                float o3 = __shfl_xor_sync(0xffffffffu, a3, 1);
                int row_l; float xi, xf, xg, xo;
                if (pair_sel == 0) { row_l = rl;     xi = a0; xf = a1; xg = o0; xo = o1; }
                else               { row_l = rl + 8; xi = o2; xf = o3; xg = a2; xo = a3; }
                const int d_l = wn * 8 + in * 2 + ((lane & 3) >> 1);
                float si = 1.f / (1.f + expf(-xi));
                float sf = 1.f / (1.f + expf(-xf));
                float so = 1.f / (1.f + expf(-xo));
                float c2 = sf * sC[row_l * 36 + d_l] + si * tanhf(xg);
                float h2 = so * tanhf(c2);
                sC[row_l * 36 + d_l] = c2;
                sH[row_l * 40 + d_l] = __float2half(h2);
            }
        }
        __syncthreads();

        // phase 3: coalesced stores (c float4, h uint4=8 halves)
#pragma unroll
        for (int k = 0; k < 4; k++) {
            int idx = tid + k * 256;
            int row = idx >> 3, q = idx & 7;
            *(float4*)(g_c + (size_t)(bm + row) * DN + d0 + q * 4) =
                ((const float4*)sC)[row * 9 + q];
        }
#pragma unroll
        for (int k = 0; k < 2; k++) {
            int idx = tid + k * 256;          // 0..511 uint4 chunks
            int row = idx >> 2, q = idx & 3;
            *(uint4*)(Xout + (size_t)(bm + row) * KA + d0 + q * 8) =
                ((const uint4*)sH)[row * 5 + q];
        }
    } else {
        // ---- pu store ----
#pragma unroll
        for (int im = 0; im < 4; im++) {
            const int r = bm + wm * 64 + im * 16 + (lane >> 2);
#pragma unroll
            for (int in = 0; in < 4; in++) {
                const int cc = bn - N4D + wn * 32 + in * 8 + (lane & 3) * 2;
                *(float2*)(PoutW + (size_t)r * NB + cc) =
                    make_float2(acc[im][in][0], acc[im][in][1]);
                *(float2*)(PoutW + (size_t)(r + 8) * NB + cc) =
                    make_float2(acc[im][in][2], acc[im][in][3]);
            }
        }
        // first pu block per band writes x_{t+1} into Xout
        if (bx == 16) {
            const int rrow = bm + (tid >> 1);
            const int jb = (tid & 1) * 16;
#pragma unroll
            for (int j = 0; j < 16; j++) {
                int jj = jb + j;
                Xout[(size_t)rrow * KA + DN + jj] =
                    __float2half(g_seq[(size_t)rrow * SEQLEN + t + 1 + jj]);
            }
        }
    }
}

// ---------------- attention kernel (step t-1), runs on side stream ----------------
__global__ __launch_bounds__(256) void attn_step(
    int t,
    const float* __restrict__ b_wp, const float* __restrict__ W_vp,
    const float* __restrict__ b_vp, const float* __restrict__ W_fc,
    const float* __restrict__ b_fc,
    float* __restrict__ outPred, float* __restrict__ outAlpha)
{
    const int b  = blockIdx.x;
    const int tid = threadIdx.x;
    const int tt = t - 1;

    __shared__ __align__(16) __half sEnc[SN * EN2];   // ~33.8 KB
    __shared__ float sU[EN];
    __shared__ float sAtt[SN];
    __shared__ float sAlpha[SN];
    __shared__ float sRed[8];
    __shared__ float sAligned;

    const float* Pr = g_Pout[t & 1] + (size_t)b * NB;

    // encoder tile -> smem (row-padded, 32 x 16B chunks per 256-half row)
    const uint4* ge = (const uint4*)(g_enc + (size_t)b * SN * EN);
#pragma unroll
    for (int i = 0; i < 8; i++) {
        int c = tid + i * 256;
        int row = c >> 5, jc = c & 31;
        cp16(smem_u32(sEnc + row * EN2 + jc * 8), ge + c);
    }
    asm volatile("cp.async.commit_group;\n");

    sU[tid] = Pr[DN + tid];   // u_e

    // aligned = S * sigmoid( sum_d tanh(p_d + b_wp_d) * W_vp_d + b_vp )
    float part = 0.f;
#pragma unroll
    for (int it = 0; it < 2; it++) {
        int d = tid + it * 256;
        part += tanhf(Pr[d] + b_wp[d]) * W_vp[d];
    }
#pragma unroll
    for (int o = 16; o; o >>= 1) part += __shfl_xor_sync(0xffffffffu, part, o);
    if ((tid & 31) == 0) sRed[tid >> 5] = part;
    __syncthreads();
    if (tid == 0) {
        float tot = 0.f;
#pragma unroll
        for (int i = 0; i < 8; i++) tot += sRed[i];
        tot += b_vp[0];
        sAligned = (float)SN / (1.f + expf(-tot));
    }
    asm volatile("cp.async.wait_group 0;\n");
    __syncthreads();
    const float aligned = sAligned;

    // att_s = <enc_s, u>
    {
        int s = tid >> 2, q = tid & 3;
        const __half* er = sEnc + s * EN2;
        float a = 0.f;
#pragma unroll 16
        for (int e = q; e < EN; e += 4) a += __half2float(er[e]) * sU[e];
        a += __shfl_xor_sync(0xffffffffu, a, 1);
        a += __shfl_xor_sync(0xffffffffu, a, 2);
        if (q == 0) sAtt[s] = a;
    }
    __syncthreads();

    // softmax + Gaussian window (warp 0)
    if (tid < 32) {
        float a0 = sAtt[tid], a1 = sAtt[tid + 32];
        float m = fmaxf(a0, a1);
#pragma unroll
        for (int o = 16; o; o >>= 1) m = fmaxf(m, __shfl_xor_sync(0xffffffffu, m, o));
        float e0 = expf(a0 - m), e1 = expf(a1 - m);
        float s2 = e0 + e1;
#pragma unroll
        for (int o = 16; o; o >>= 1) s2 += __shfl_xor_sync(0xffffffffu, s2, o);
        float inv = 1.f / s2;
        float d0 = (float)tid - aligned, d1 = (float)(tid + 32) - aligned;
        sAlpha[tid]      = e0 * inv * expf(-0.5f * d0 * d0);
        sAlpha[tid + 32] = e1 * inv * expf(-0.5f * d1 * d1);
    }
    __syncthreads();

    if (tid < SN)
        outAlpha[((size_t)b * TN + tt) * SN + tid] = sAlpha[tid];

    // awe + pred (h_{t-1} read as fp16 from Xcat[t%3])
    float awe = 0.f;
#pragma unroll 16
    for (int s = 0; s < SN; s++) awe += __half2float(sEnc[s * EN2 + tid]) * sAlpha[s];

    const __half* hrow = g_Xcat[t % 3] + (size_t)b * KA;
    float pp = awe * W_fc[tid]
             + __half2float(hrow[tid])       * W_fc[EN + tid]
             + __half2float(hrow[tid + 256]) * W_fc[EN + 256 + tid];
#pragma unroll
    for (int o = 16; o; o >>= 1) pp += __shfl_xor_sync(0xffffffffu, pp, o);
    if ((tid & 31) == 0) sRed[tid >> 5] = pp;
    __syncthreads();
    if (tid == 0) {
        float tot = 0.f;
#pragma unroll
        for (int i = 0; i < 8; i++) tot += sRed[i];
        outPred[(size_t)b * TN + tt] = tot + b_fc[0];
    }
}

// ---------------- init GEMM (h0|c0) ----------------
__global__ __launch_bounds__(256, 2) void gemmI_kernel() {
    extern __shared__ char dynsmem[];
    float acc[4][4][4];
    const int bm = blockIdx.y * BM;
    const int bn = blockIdx.x * BN;
    gemm_mainloop<288, 288, 1024>(g_Inp, g_WiT, bm, bn, acc, dynsmem);
    const int tid  = threadIdx.x;
    const int lane = tid & 31;
    const int warp = tid >> 5;
    const int wm   = warp & 1;
    const int wn   = warp >> 1;
#pragma unroll
    for (int im = 0; im < 4; im++) {
        const int r = bm + wm * 64 + im * 16 + (lane >> 2);
#pragma unroll
        for (int in = 0; in < 4; in++) {
            const int cc = bn + wn * 32 + in * 8 + (lane & 3) * 2;
            *(float2*)(g_gates + (size_t)r * 1024 + cc) =
                make_float2(acc[im][in][0], acc[im][in][1]);
            *(float2*)(g_gates + (size_t)(r + 8) * 1024 + cc) =
                make_float2(acc[im][in][2], acc[im][in][3]);
        }
    }
}

// ---------------- init / pack kernels ----------------
__global__ void pack_wf(const float* __restrict__ W_hh, const float* __restrict__ W_ih,
                        const float* __restrict__ W_wp, const float* __restrict__ W_wa,
                        const float* __restrict__ b_ih, const float* __restrict__ b_hh) {
    int idx = blockIdx.x * 256 + threadIdx.x;
    if (idx < N4D) {
        int d = idx >> 2, g = idx & 3;
        g_gb[idx] = b_ih[g * DN + d] + b_hh[g * DN + d];
    }
    if (idx >= KA * NF) return;
    int k = idx / NF, n = idx - k * NF;
    float v;
    if (n < N4D) {
        int d = n >> 2, g = n & 3;
        int gr = g * DN + d;
        v = (k < DN) ? W_hh[(size_t)gr * DN + k] : W_ih[(size_t)gr * INN + (k - DN)];
    } else if (n < N4D + DN) {
        int d = n - N4D;
        v = (k < DN) ? W_wp[(size_t)d * DN + k] : 0.f;
    } else {
        int e = n - N4D - DN;
        v = (k < DN) ? W_wa[(size_t)k * EN + e] : 0.f;
    }
    g_WfT[idx] = __float2half(v);
}
__global__ void pack_wi(const float* __restrict__ W_init_h, const float* __restrict__ W_init_c) {
    int idx = blockIdx.x * 256 + threadIdx.x;
    if (idx >= 288 * 1024) return;
    int k = idx / 1024, n = idx - k * 1024;
    float v = (n < DN) ? W_init_h[(size_t)n * 288 + k] : W_init_c[(size_t)(n - DN) * 288 + k];
    g_WiT[idx] = __float2half(v);
}
__global__ void enc_convert(const float* __restrict__ src) {
    size_t i = (size_t)blockIdx.x * 256 + threadIdx.x;
    const size_t n4 = (size_t)BATCH * SN * EN / 4;
    if (i >= n4) return;
    float4 v = ((const float4*)src)[i];
    __half2* dst = (__half2*)g_enc;
    dst[2 * i]     = __floats2half2_rn(v.x, v.y);
    dst[2 * i + 1] = __floats2half2_rn(v.z, v.w);
}
__global__ void seq_build(const float* __restrict__ hist, const float* __restrict__ cur) {
    int idx = blockIdx.x * 256 + threadIdx.x;
    if (idx >= BATCH * SEQLEN) return;
    int b = idx / SEQLEN, j = idx - b * SEQLEN;
    float v = (j < 31) ? hist[(size_t)b * 31 + j]
            : (j < 95) ? cur[(size_t)b * TN + (j - 31)] : 0.f;
    g_seq[idx] = v;
}
__global__ void mean_inp(const float* __restrict__ cEnc) {
    int b = blockIdx.x, tid = threadIdx.x;
    const float* p = cEnc + (size_t)b * SN * EN + tid;
    float s = 0.f;
#pragma unroll 8
    for (int i = 0; i < SN; i++) s += p[(size_t)i * EN];
    g_Inp[(size_t)b * 288 + tid] = __float2half(s * (1.f / 64.f));
    if (tid < INN)
        g_Inp[(size_t)b * 288 + EN + tid] = __float2half(g_seq[(size_t)b * SEQLEN + tid]);
}
__global__ void init_finish(const float* __restrict__ b_init_h, const float* __restrict__ b_init_c) {
    int idx = blockIdx.x * 256 + threadIdx.x;
    if (idx >= BATCH * KA) return;
    int b = idx / KA, d = idx - b * KA;
    if (d < DN) {
        float h0 = g_gates[(size_t)b * 1024 + d] + b_init_h[d];
        float c0 = g_gates[(size_t)b * 1024 + DN + d] + b_init_c[d];
        g_c[(size_t)b * DN + d] = c0;
        g_Xcat[0][idx] = __float2half(h0);
    } else {
        g_Xcat[0][idx] = __float2half(g_seq[(size_t)b * SEQLEN + (d - DN)]);  // x_0
    }
}

// ---------------- per-process stream/event resources (host-side only) ----------------
struct StepRes {
    cudaStream_t s2;
    cudaEvent_t em[TN + 1];   // end of fused_gemm(t) on main stream
    cudaEvent_t ea[TN + 1];   // end of attn launched in iteration t on s2
    StepRes() {
        cudaStreamCreateWithFlags(&s2, cudaStreamNonBlocking);
        for (int i = 0; i <= TN; i++) {
            cudaEventCreateWithFlags(&em[i], cudaEventDisableTiming);
            cudaEventCreateWithFlags(&ea[i], cudaEventDisableTiming);
        }
    }
};

// ---------------- launcher ----------------
extern "C" void kernel_launch(void* const* d_in, const int* in_sizes, int n_in,
                              void* d_out, int out_size) {
    static StepRes R;   // host resources only; created eagerly on first (non-capture) call

    const float* cEnc       = (const float*)d_in[0];
    const float* curSpeeds  = (const float*)d_in[1];
    const float* histSpeeds = (const float*)d_in[2];
    int wo = (n_in > 5 && in_sizes[5] == 1) ? 6 : 5;
    const float* W_init_h = (const float*)d_in[wo + 0];
    const float* b_init_h = (const float*)d_in[wo + 1];
    const float* W_init_c = (const float*)d_in[wo + 2];
    const float* b_init_c = (const float*)d_in[wo + 3];
    const float* W_ih     = (const float*)d_in[wo + 4];
    const float* W_hh     = (const float*)d_in[wo + 5];
    const float* b_ih     = (const float*)d_in[wo + 6];
    const float* b_hh     = (const float*)d_in[wo + 7];
    const float* W_wa     = (const float*)d_in[wo + 8];
    // b_wa (wo+9) is softmax-invariant: unused
    const float* W_wp     = (const float*)d_in[wo + 10];
    const float* b_wp     = (const float*)d_in[wo + 11];
    const float* W_vp     = (const float*)d_in[wo + 12];
    const float* b_vp     = (const float*)d_in[wo + 13];
    const float* W_fc     = (const float*)d_in[wo + 14];
    const float* b_fc     = (const float*)d_in[wo + 15];

    float* outPred  = (float*)d_out;                 // [B,T,1]
    float* outAlpha = outPred + (size_t)BATCH * TN;  // [B,T,S]

    cudaFuncSetAttribute(fused_gemm, cudaFuncAttributeMaxDynamicSharedMemorySize, DYN_SMEM);
    cudaFuncSetAttribute(gemmI_kernel, cudaFuncAttributeMaxDynamicSharedMemorySize, DYN_SMEM);

    enc_convert<<<32768, 256>>>(cEnc);
    seq_build<<<(BATCH * SEQLEN) / 256, 256>>>(histSpeeds, curSpeeds);
    pack_wf<<<(KA * NF + 255) / 256, 256>>>(W_hh, W_ih, W_wp, W_wa, b_ih, b_hh);
    pack_wi<<<(288 * 1024) / 256, 256>>>(W_init_h, W_init_c);
    mean_inp<<<BATCH, 256>>>(cEnc);
    gemmI_kernel<<<dim3(1024 / BN, BATCH / BM), 256, DYN_SMEM>>>();
    init_finish<<<(BATCH * KA) / 256, 256>>>(b_init_h, b_init_c);

    // Software pipeline:
    //   main stream: fused_gemm(t) — gates_t (+LSTM -> Xcat[(t+1)%3]) and pu_{t-1}
    //                (into Pout[t&1]); waits ea[t-2] (buffer anti-dependency).
    //   s2 stream:   attn for step t-1 after em[t]; overlaps fused_gemm(t+1).
    for (int t = 0; t <= TN; t++) {
        if (t >= 3) cudaStreamWaitEvent(0, R.ea[t - 2], 0);
        fused_gemm<<<352, 256, DYN_SMEM>>>(t);
        cudaEventRecord(R.em[t], 0);
        if (t >= 1) {
            cudaStreamWaitEvent(R.s2, R.em[t], 0);
            attn_step<<<BATCH, 256, 0, R.s2>>>(t, b_wp, W_vp, b_vp, W_fc, b_fc,
                                               outPred, outAlpha);
            cudaEventRecord(R.ea[t], R.s2);
        }
    }
    // join the forked stream back into the capture-origin stream
    cudaStreamWaitEvent(0, R.ea[TN - 1], 0);
    cudaStreamWaitEvent(0, R.ea[TN], 0);
}